// round 17
// baseline (speedup 1.0000x reference)
#include <cuda_runtime.h>
#include <math.h>
#include <cstdint>

#define NN 8192
#define FF 256
#define DD 64
#define KH 2
#define JSPLIT 8

#define GEMM_CTAS (NN / 32)      // 256
#define MASK_CTAS (NN / 8)       // 1024

// ---------------- scratch (static device globals; no allocation) -------------
__device__ unsigned g_HWp[KH*(NN/2)*DD]; // [k][j/2][d] half2{HW[2jj][d],HW[2jj+1][d]}
__device__ float  g_rho[KH*NN];          // exp(-0.8*e1) = p51/p1
__device__ float2 g_ip2[KH*NN];          // {p2=exp(e2), p52=exp(0.2*e2)}
__device__ uint2  g_jph[KH*(NN/2)];      // {half2{q1 even,q1 odd}, half2{q5 even,q5 odd}}
__device__ unsigned g_mask[NN*(NN/32)];  // bitpacked A, row-major [j][i/32]
__device__ float g_part[JSPLIT*KH*NN*DD]; // partial outputs [s][k][i][d]

// ---------------- small PTX helpers (plain sm_80+ PTX) ----------------------
__device__ __forceinline__ unsigned pack_h2(float lo, float hi) {
    unsigned r;
    asm("cvt.rn.f16x2.f32 %0, %1, %2;" : "=r"(r) : "f"(hi), "f"(lo));
    return r;
}
__device__ __forceinline__ unsigned hmul2(unsigned a, unsigned b) {
    unsigned r;
    asm("mul.rn.f16x2 %0, %1, %2;" : "=r"(r) : "r"(a), "r"(b));
    return r;
}
__device__ __forceinline__ unsigned hmax2(unsigned a, unsigned b) {
    unsigned r;
    asm("max.f16x2 %0, %1, %2;" : "=r"(r) : "r"(a), "r"(b));
    return r;
}
// Two-source PRMT with sign-replicate nibbles (bit3). __byte_perm's contract
// covers only 3-bit selectors, so replicate mode must use inline asm.
__device__ __forceinline__ unsigned prmt2(unsigned a, unsigned b, unsigned sel) {
    unsigned r;
    asm("prmt.b32 %0, %1, %2, %3;" : "=r"(r) : "r"(a), "r"(b), "r"(sel));
    return r;
}
__device__ __forceinline__ void mma_f16(float* d, const unsigned* a, const unsigned* bf) {
    asm volatile(
        "mma.sync.aligned.m16n8k16.row.col.f32.f16.f16.f32 "
        "{%0,%1,%2,%3}, {%4,%5,%6,%7}, {%8,%9}, {%0,%1,%2,%3};"
        : "+f"(d[0]), "+f"(d[1]), "+f"(d[2]), "+f"(d[3])
        : "r"(a[0]), "r"(a[1]), "r"(a[2]), "r"(a[3]), "r"(bf[0]), "r"(bf[1]));
}

// ------- kernel 1 (fused): A-bitpack CTAs + HW-GEMM CTAs in one launch ------
// CTAs [0, MASK_CTAS): bitpack 8 rows of A each (pure DRAM sweep).
// CTAs [MASK_CTAS, MASK_CTAS+GEMM_CTAS): HW = H@W for a 32-row tile, packed
//   half2 output, PLUS fused e1/e2 epilogue (shfl butterfly) -> g_rho/g_ip2.
__global__ void __launch_bounds__(256) k_hwmask(
    const float* __restrict__ H, const float* __restrict__ W,
    const float* __restrict__ a1, const float* __restrict__ a2,
    const int* __restrict__ A
) {
    __shared__ float Ws[64][128];
    __shared__ float Hs[32][64];
    __shared__ float a1s[128], a2s[128];

    const int tid = threadIdx.x;

    if (blockIdx.x < MASK_CTAS) {
        // ---------------- bitpack role ----------------
        const int lane = tid & 31, wrp = tid >> 5;
        const int j0 = blockIdx.x * 8;
        for (int ci = 0; ci < 32; ci++) {
            const int col = ci * 256 + tid;
#pragma unroll
            for (int j = 0; j < 8; j++) {
                int a = A[(size_t)(j0 + j) * NN + col];
                unsigned bal = __ballot_sync(0xffffffffu, a != 0);
                if (lane == 0) g_mask[(j0 + j) * (NN / 32) + ci * 8 + wrp] = bal;
            }
        }
        return;
    }

    // ---------------- GEMM + e-epilogue role ----------------
    const int tx = tid & 31;
    const int ty = tid >> 5;
    const int n0 = (blockIdx.x - MASK_CTAS) * 32;

    if (tid < 128) a1s[tid] = a1[tid];
    else           a2s[tid - 128] = a2[tid - 128];

    float acc[4][4];
#pragma unroll
    for (int a = 0; a < 4; a++)
#pragma unroll
        for (int b = 0; b < 4; b++) acc[a][b] = 0.f;

    for (int fc = 0; fc < FF; fc += 64) {
#pragma unroll
        for (int q = 0; q < 8; q++) {
            int idx = q * 256 + tid;
            int kk = idx >> 5, c4 = idx & 31;
            int c = c4 * 4;
            int k = c >> 6, d = c & 63;
            float4 v = *(const float4*)(W + k * (FF * DD) + (fc + kk) * DD + d);
            *(float4*)(&Ws[kk][c]) = v;
        }
#pragma unroll
        for (int q = 0; q < 2; q++) {
            int idx = q * 256 + tid;
            int r = idx >> 4, k4 = idx & 15;
            float4 v = *(const float4*)(H + (n0 + r) * FF + fc + k4 * 4);
            *(float4*)(&Hs[r][k4 * 4]) = v;
        }
        __syncthreads();
#pragma unroll 8
        for (int kk = 0; kk < 64; kk++) {
            float4 bv = *(const float4*)(&Ws[kk][tx * 4]);
            float a0 = Hs[ty * 4 + 0][kk];
            float a1v = Hs[ty * 4 + 1][kk];
            float a2v = Hs[ty * 4 + 2][kk];
            float a3 = Hs[ty * 4 + 3][kk];
            acc[0][0] += a0 * bv.x;  acc[0][1] += a0 * bv.y;  acc[0][2] += a0 * bv.z;  acc[0][3] += a0 * bv.w;
            acc[1][0] += a1v * bv.x; acc[1][1] += a1v * bv.y; acc[1][2] += a1v * bv.z; acc[1][3] += a1v * bv.w;
            acc[2][0] += a2v * bv.x; acc[2][1] += a2v * bv.y; acc[2][2] += a2v * bv.z; acc[2][3] += a2v * bv.w;
            acc[3][0] += a3 * bv.x;  acc[3][1] += a3 * bv.y;  acc[3][2] += a3 * bv.z;  acc[3][3] += a3 * bv.w;
        }
        __syncthreads();
    }

    const int k = (tx * 4) >> 6;
    // packed half2 HW copy: rows (2jj, 2jj+1)
    {
        const int d = (tx * 4) & 63;
        const int jj0 = ((n0 + ty * 4) >> 1);
        uint4 w0, w1;
        w0.x = pack_h2(acc[0][0], acc[1][0]);
        w0.y = pack_h2(acc[0][1], acc[1][1]);
        w0.z = pack_h2(acc[0][2], acc[1][2]);
        w0.w = pack_h2(acc[0][3], acc[1][3]);
        w1.x = pack_h2(acc[2][0], acc[3][0]);
        w1.y = pack_h2(acc[2][1], acc[3][1]);
        w1.z = pack_h2(acc[2][2], acc[3][2]);
        w1.w = pack_h2(acc[2][3], acc[3][3]);
        *(uint4*)(g_HWp + ((size_t)(k * (NN / 2) + jj0) * DD + d))     = w0;
        *(uint4*)(g_HWp + ((size_t)(k * (NN / 2) + jj0 + 1) * DD + d)) = w1;
    }

    // fused e1/e2: per-thread partials over this thread's 4 d-columns, then
    // butterfly-reduce across the 16 lanes of the same head.
    float pe1[4], pe2[4];
#pragma unroll
    for (int s = 0; s < 4; s++) {
        const float* A1 = a1s + tx * 4;   // == a1[k*64 + d]
        const float* A2 = a2s + tx * 4;
        pe1[s] = acc[s][0] * A1[0] + acc[s][1] * A1[1] + acc[s][2] * A1[2] + acc[s][3] * A1[3];
        pe2[s] = acc[s][0] * A2[0] + acc[s][1] * A2[1] + acc[s][2] * A2[2] + acc[s][3] * A2[3];
    }
#pragma unroll
    for (int m = 1; m < 16; m <<= 1) {
#pragma unroll
        for (int s = 0; s < 4; s++) {
            pe1[s] += __shfl_xor_sync(0xffffffffu, pe1[s], m);
            pe2[s] += __shfl_xor_sync(0xffffffffu, pe2[s], m);
        }
    }
    if ((tx & 3) == 0) {
        const int s = (tx >> 2) & 3;       // lanes 0/4/8/12 (and 16/20/24/28)
        const int row = n0 + ty * 4 + s;
        const int gi = k * NN + row;
        g_rho[gi] = expf(-0.8f * pe1[s]);
        g_ip2[gi] = make_float2(expf(pe2[s]), expf(0.2f * pe2[s]));
    }
}

// ------- kernel 2: softmax denominators from BITMASK (max-trick) -------------
// Z[j] = p1 * sum_i am * max(p2_i, rho_j*p52_i). Mask word is warp-uniform.
__global__ void k_z(int dummy) {
    __shared__ float red[16][8];
    __shared__ float qtmp[2][8][2];
    const int tid = threadIdx.x;
    const int lane = tid & 31, wrp = tid >> 5;
    const int j0 = blockIdx.x * 8;

    float rho[8][2];
#pragma unroll
    for (int j = 0; j < 8; j++) {
        rho[j][0] = g_rho[j0 + j];
        rho[j][1] = g_rho[NN + j0 + j];
    }
    float z[8][2];
#pragma unroll
    for (int j = 0; j < 8; j++) { z[j][0] = 0.f; z[j][1] = 0.f; }

    for (int ci = 0; ci < 32; ci++) {
        const int col = ci * 256 + tid;
        const float2 ip0 = g_ip2[col];
        const float2 ip1 = g_ip2[NN + col];
#pragma unroll
        for (int j = 0; j < 8; j++) {
            unsigned mw = g_mask[(j0 + j) * (NN / 32) + ci * 8 + wrp];
            float am = ((mw >> lane) & 1u) ? 1.0f : 0.0f;
            z[j][0] += am * fmaxf(ip0.x, rho[j][0] * ip0.y);
            z[j][1] += am * fmaxf(ip1.x, rho[j][1] * ip1.y);
        }
    }
#pragma unroll
    for (int v = 0; v < 16; v++) {
        int j = v >> 1, k = v & 1;
        float val = z[j][k];
        val += __shfl_down_sync(0xffffffffu, val, 16);
        val += __shfl_down_sync(0xffffffffu, val, 8);
        val += __shfl_down_sync(0xffffffffu, val, 4);
        val += __shfl_down_sync(0xffffffffu, val, 2);
        val += __shfl_down_sync(0xffffffffu, val, 1);
        if (lane == 0) red[v][wrp] = val;
    }
    __syncthreads();
    if (tid < 16) {
        int j = tid >> 1, k = tid & 1;
        float s = 0.f;
#pragma unroll
        for (int w = 0; w < 8; w++) s += red[tid][w];
        int gi = k * NN + j0 + j;
        float q1 = 1.0f / s;
        float q5 = g_rho[gi] * q1;
        qtmp[k][j][0] = q1;
        qtmp[k][j][1] = q5;
    }
    __syncthreads();
    if (tid < 8) {
        int k = tid >> 2, p = tid & 3;     // pair p covers j = 2p, 2p+1
        uint2 w;
        w.x = pack_h2(qtmp[k][2 * p][0], qtmp[k][2 * p + 1][0]);
        w.y = pack_h2(qtmp[k][2 * p][1], qtmp[k][2 * p + 1][1]);
        g_jph[k * (NN / 2) + (j0 >> 1) + p] = w;
    }
}

// ------- kernel 3 (f16 mma, m32n64 warps, i-tile 128 / 4 warps) -------------
// UNCHANGED from round 16 (73.4us).
__global__ void __launch_bounds__(128) k_out_mma(float* __restrict__ part) {
    __shared__ __align__(16) unsigned Bs[2][16][72];  // half2{2jj,2jj+1}, [jj][d]
    __shared__ uint2    jtabh[2][16];       // per j-pair: {q1pair, q5pair}
    __shared__ unsigned maskt[2][32][4];    // [j][word]

    const int tid  = threadIdx.x;
    const int lane = tid & 31;
    const int wid  = tid >> 5;              // 0..3
    const int kh   = blockIdx.y;
    const int spl  = blockIdx.z;
    const int i0   = blockIdx.x * 128;
    const int kbase = kh * NN;
    const int kb2   = kh * (NN / 2);
    const int mrow0 = i0 >> 5;
    const int jt0  = spl * (NN / 32 / JSPLIT);     // 32 tiles per split
    const int jt1  = jt0 + (NN / 32 / JSPLIT);

    const int rr = lane >> 2;           // 0..7
    const int cc = lane & 3;            // 0..3

    unsigned p2b[2][2], p52b[2][2];
#pragma unroll
    for (int b = 0; b < 2; b++)
#pragma unroll
        for (int h = 0; h < 2; h++) {
            float2 f = g_ip2[kbase + i0 + wid * 32 + b * 16 + h * 8 + rr];
            p2b[b][h]  = pack_h2(f.x, f.x);
            p52b[b][h] = pack_h2(f.y, f.y);
        }

    const int bjj = tid >> 3;
    const int bu0 = (tid & 7) * 8;
    const int mjj = tid >> 2;
    const int mword = tid & 3;

    uint4 rBu0, rBu1;
    uint2 rJ2;
    unsigned rM = 0;

#define LDG_TILE(JT) do {                                                        \
    const int jj0_ = (JT) * 16;                                                  \
    const unsigned* src_ = g_HWp + ((size_t)(kb2 + jj0_ + bjj) * DD + bu0);      \
    rBu0 = *(const uint4*)(src_);                                                \
    rBu1 = *(const uint4*)(src_ + 4);                                            \
    rM = g_mask[((JT) * 32 + mjj) * (NN / 32) + mrow0 + mword];                  \
    if (tid < 16) rJ2 = g_jph[kb2 + jj0_ + tid];                                 \
} while (0)

#define STS_TILE(BUF) do {                                                       \
    *(uint4*)(&Bs[BUF][bjj][bu0])     = rBu0;                                    \
    *(uint4*)(&Bs[BUF][bjj][bu0 + 4]) = rBu1;                                    \
    maskt[BUF][mjj][mword] = rM;                                                 \
    if (tid < 16) jtabh[BUF][tid] = rJ2;                                         \
} while (0)

    float acc[2][8][4];
#pragma unroll
    for (int b = 0; b < 2; b++)
#pragma unroll
        for (int nb = 0; nb < 8; nb++)
#pragma unroll
            for (int q = 0; q < 4; q++) acc[b][nb][q] = 0.f;

    LDG_TILE(jt0);
    STS_TILE(0);
    __syncthreads();

    for (int jt = jt0; jt < jt1; jt++) {
        const int bf = (jt - jt0) & 1;
        if (jt + 1 < jt1) LDG_TILE(jt + 1);

#pragma unroll
        for (int kg = 0; kg < 2; kg++) {
            const int pa = kg * 8 + cc;
            const uint2 qa = jtabh[bf][pa];
            const uint2 qc = jtabh[bf][pa + 4];
            const int ja = 2 * pa;
            const unsigned ta = ((maskt[bf][ja][wid]     >> rr) << 7) & 0x80808080u;
            const unsigned tb = ((maskt[bf][ja + 1][wid] >> rr) << 7) & 0x80808080u;
            const unsigned tc = ((maskt[bf][ja + 8][wid] >> rr) << 7) & 0x80808080u;
            const unsigned td = ((maskt[bf][ja + 9][wid] >> rr) << 7) & 0x80808080u;

            unsigned va[2][2], vc[2][2];
#pragma unroll
            for (int b = 0; b < 2; b++)
#pragma unroll
                for (int h = 0; h < 2; h++) {
                    va[b][h] = hmax2(hmul2(qa.x, p2b[b][h]), hmul2(qa.y, p52b[b][h]));
                    vc[b][h] = hmax2(hmul2(qc.x, p2b[b][h]), hmul2(qc.y, p52b[b][h]));
                }

            unsigned afr[2][4];
            afr[0][0] = va[0][0] & prmt2(ta, tb, 0xCC88u);
            afr[0][1] = va[0][1] & prmt2(ta, tb, 0xDD99u);
            afr[0][2] = vc[0][0] & prmt2(tc, td, 0xCC88u);
            afr[0][3] = vc[0][1] & prmt2(tc, td, 0xDD99u);
            afr[1][0] = va[1][0] & prmt2(ta, tb, 0xEEAAu);
            afr[1][1] = va[1][1] & prmt2(ta, tb, 0xFFBBu);
            afr[1][2] = vc[1][0] & prmt2(tc, td, 0xEEAAu);
            afr[1][3] = vc[1][1] & prmt2(tc, td, 0xFFBBu);

            const int jjb = kg * 8 + cc;
#pragma unroll
            for (int nb = 0; nb < 8; nb++) {
                unsigned bfr[2];
                bfr[0] = Bs[bf][jjb][nb * 8 + rr];
                bfr[1] = Bs[bf][jjb + 4][nb * 8 + rr];
                mma_f16(acc[0][nb], afr[0], bfr);
                mma_f16(acc[1][nb], afr[1], bfr);
            }
        }

        if (jt + 1 < jt1) STS_TILE(bf ^ 1);
        __syncthreads();
    }

    float* pbase = part + ((size_t)(spl * KH + kh) * NN) * DD;
#pragma unroll
    for (int b = 0; b < 2; b++) {
        const int ilo = i0 + wid * 32 + b * 16 + rr;
#pragma unroll
        for (int nb = 0; nb < 8; nb++) {
            int col = nb * 8 + 2 * cc;
            *(float2*)(pbase + (size_t)ilo * DD + col) =
                make_float2(acc[b][nb][0], acc[b][nb][1]);
            *(float2*)(pbase + (size_t)(ilo + 8) * DD + col) =
                make_float2(acc[b][nb][2], acc[b][nb][3]);
        }
    }
#undef LDG_TILE
#undef STS_TILE
}

// ------- kernel 4: reduce partials + bias + relu ----------------------------
__global__ void k_fin(const float* __restrict__ bias, float* __restrict__ out) {
    const int t = blockIdx.x * 256 + threadIdx.x;   // float4 id over [NN][K*D]
    const int d4 = t & 31;
    const int i  = t >> 5;
    const int kh = d4 >> 4;
    const int dd4 = d4 & 15;
    const size_t pidx = (((size_t)kh * NN + i) * DD + dd4 * 4) / 4;

    const float4* P = (const float4*)g_part;
    const size_t stride4 = (size_t)KH * NN * DD / 4;
    float4 acc = P[pidx];
#pragma unroll
    for (int s = 1; s < JSPLIT; s++) {
        float4 v = P[pidx + (size_t)s * stride4];
        acc.x += v.x; acc.y += v.y; acc.z += v.z; acc.w += v.w;
    }
    float4 bv = *(const float4*)(bias + kh * DD + dd4 * 4);
    float4 o;
    o.x = fmaxf(acc.x + bv.x, 0.f);
    o.y = fmaxf(acc.y + bv.y, 0.f);
    o.z = fmaxf(acc.z + bv.z, 0.f);
    o.w = fmaxf(acc.w + bv.w, 0.f);
    ((float4*)out)[t] = o;
}

// ---------------------------------------------------------------------------
extern "C" void kernel_launch(void* const* d_in, const int* in_sizes, int n_in,
                              void* d_out, int out_size) {
    const float* H  = (const float*)d_in[0];   // [8192,256]
    const int*   A  = (const int*)  d_in[1];   // [8192,8192]
    const float* W  = (const float*)d_in[2];   // [2,256,64]
    const float* b  = (const float*)d_in[3];   // [2,64]
    const float* a1 = (const float*)d_in[4];   // [2,64]
    const float* a2 = (const float*)d_in[5];   // [2,64]
    float* out = (float*)d_out;                // [8192,128]

    float* part;
    cudaGetSymbolAddress((void**)&part, g_part);

    k_hwmask<<<MASK_CTAS + GEMM_CTAS, 256>>>(H, W, a1, a2, A);
    k_z<<<NN / 8, 256>>>(0);
    k_out_mma<<<dim3(NN / 128, KH, JSPLIT), 128>>>(part);
    k_fin<<<(NN * KH * DD / 4) / 256, 256>>>(b, out);
}